// round 1
// baseline (speedup 1.0000x reference)
#include <cuda_runtime.h>

// Problem constants (from reference): B=128, C=3, H=W=256, PROB=0.9,
// BRI=CON=SAT=0.2, CUT=0.25 -> CH=CW=64.
#define B_   128
#define C_   3
#define H_   256
#define W_   256
#define CH_  64
#define CW_  64
#define PROB_ 0.9f

static constexpr int PLANE = H_ * W_;      // 65536 floats per (b,c) plane
static constexpr int PLANE4 = PLANE / 4;   // float4 count per plane

// Scratch for per-(b,c) plane means (allocation-free rule: __device__ global).
__device__ float g_mean[B_ * C_];

// ---------------------------------------------------------------------------
// Pass 1: per-plane mean of the RAW images. 384 blocks, one per (b,c) plane.
// Each thread sequentially sums 64 float4 (256 values) -> warp/block reduce.
// ---------------------------------------------------------------------------
__global__ __launch_bounds__(256) void mean_kernel(const float* __restrict__ img) {
    __shared__ float sm[8];
    const int plane = blockIdx.x;  // 0..383
    const float4* p = reinterpret_cast<const float4*>(img) + (size_t)plane * PLANE4;

    float acc = 0.0f;
#pragma unroll 4
    for (int i = threadIdx.x; i < PLANE4; i += 256) {
        float4 v = __ldg(p + i);
        acc += (v.x + v.y) + (v.z + v.w);
    }
#pragma unroll
    for (int o = 16; o > 0; o >>= 1)
        acc += __shfl_xor_sync(0xFFFFFFFFu, acc, o);
    if ((threadIdx.x & 31) == 0) sm[threadIdx.x >> 5] = acc;
    __syncthreads();
    if (threadIdx.x < 8) {
        float v = sm[threadIdx.x];
#pragma unroll
        for (int o = 4; o > 0; o >>= 1)
            v += __shfl_xor_sync(0xFFu, v, o);
        if (threadIdx.x == 0)
            g_mean[plane] = v * (1.0f / (float)PLANE);
    }
}

// ---------------------------------------------------------------------------
// Pass 2: fused flip + brightness + contrast + saturation + cutout + apply.
//
// Algebra: with b,c,s the per-batch factors and x0 the (possibly flipped)
// raw pixel, M1_ch = b*mean(raw plane), M1bar = mean_ch(M1):
//   out_ch = A*x0_ch + D*g0 + E_ch
//   A = s*b*c ; D = (1-s)*b*c ; g0 = (x0_r + x0_g + x0_b)/3
//   E_ch = (1-c) * ( s*M1_ch + (1-s)*M1bar )
// Then cutout-zero inside the box, and apply_u >= PROB selects raw input.
//
// Block = 256 threads = 4 rows x 64 float4 column-groups of one batch.
// Grid = (H/4, B).
// ---------------------------------------------------------------------------
__global__ __launch_bounds__(256) void aug_kernel(
    const float* __restrict__ img,
    const float* __restrict__ apply_u,
    const float* __restrict__ flip_u,
    const float* __restrict__ bri_u,
    const float* __restrict__ con_u,
    const float* __restrict__ sat_u,
    const int*   __restrict__ top_idx,
    const int*   __restrict__ left_idx,
    float* __restrict__ out)
{
    const int b   = blockIdx.y;
    const int tid = threadIdx.x;
    const int h   = blockIdx.x * 4 + (tid >> 6);  // row
    const int wg  = tid & 63;                     // float4 column group
    const int w0  = wg << 2;                      // first column of the group

    const size_t rowbase = (size_t)b * (3 * PLANE) + (size_t)h * W_;
    const float4* inR  = reinterpret_cast<const float4*>(img + rowbase);
    const float4* inG  = reinterpret_cast<const float4*>(img + rowbase + PLANE);
    const float4* inB  = reinterpret_cast<const float4*>(img + rowbase + 2 * PLANE);
    float4* outR = reinterpret_cast<float4*>(out + rowbase);
    float4* outG = reinterpret_cast<float4*>(out + rowbase + PLANE);
    float4* outB = reinterpret_cast<float4*>(out + rowbase + 2 * PLANE);

    const bool apply = (__ldg(apply_u + b) < PROB_);

    if (!apply) {
        // Pure copy path (uniform per block — no divergence).
        outR[wg] = __ldg(inR + wg);
        outG[wg] = __ldg(inG + wg);
        outB[wg] = __ldg(inB + wg);
        return;
    }

    const bool flip = (__ldg(flip_u + b) < 0.5f);
    const int  sw   = flip ? (W_ / 4 - 1 - wg) : wg;

    float4 r = __ldg(inR + sw);
    float4 g = __ldg(inG + sw);
    float4 c = __ldg(inB + sw);
    if (flip) {
        float t;
        t = r.x; r.x = r.w; r.w = t;  t = r.y; r.y = r.z; r.z = t;
        t = g.x; g.x = g.w; g.w = t;  t = g.y; g.y = g.z; g.z = t;
        t = c.x; c.x = c.w; c.w = t;  t = c.y; c.y = c.z; c.z = t;
    }

    const float bv = 0.8f + 0.4f * __ldg(bri_u + b);
    const float cv = 0.8f + 0.4f * __ldg(con_u + b);
    const float sv = 0.8f + 0.4f * __ldg(sat_u + b);

    const float M0 = g_mean[b * 3 + 0] * bv;
    const float M1 = g_mean[b * 3 + 1] * bv;
    const float M2 = g_mean[b * 3 + 2] * bv;
    const float Mbar = (M0 + M1 + M2) * (1.0f / 3.0f);

    const float A  = sv * bv * cv;
    const float D  = (1.0f - sv) * bv * cv;
    const float k  = 1.0f - cv;
    const float os = 1.0f - sv;
    const float E0 = k * (sv * M0 + os * Mbar);
    const float E1 = k * (sv * M1 + os * Mbar);
    const float E2 = k * (sv * M2 + os * Mbar);

    const int t_ = __ldg(top_idx + b);
    const int l_ = __ldg(left_idx + b);
    const bool row_in = (h >= t_) && (h < t_ + CH_);

    float4 oR, oG, oB;
    {
        // lane 0..3
        float gray;
        bool cut;
        int col;

        col = w0 + 0; cut = row_in && (col >= l_) && (col < l_ + CW_);
        gray = (r.x + g.x + c.x) * (1.0f / 3.0f);
        oR.x = cut ? 0.0f : fmaf(A, r.x, fmaf(D, gray, E0));
        oG.x = cut ? 0.0f : fmaf(A, g.x, fmaf(D, gray, E1));
        oB.x = cut ? 0.0f : fmaf(A, c.x, fmaf(D, gray, E2));

        col = w0 + 1; cut = row_in && (col >= l_) && (col < l_ + CW_);
        gray = (r.y + g.y + c.y) * (1.0f / 3.0f);
        oR.y = cut ? 0.0f : fmaf(A, r.y, fmaf(D, gray, E0));
        oG.y = cut ? 0.0f : fmaf(A, g.y, fmaf(D, gray, E1));
        oB.y = cut ? 0.0f : fmaf(A, c.y, fmaf(D, gray, E2));

        col = w0 + 2; cut = row_in && (col >= l_) && (col < l_ + CW_);
        gray = (r.z + g.z + c.z) * (1.0f / 3.0f);
        oR.z = cut ? 0.0f : fmaf(A, r.z, fmaf(D, gray, E0));
        oG.z = cut ? 0.0f : fmaf(A, g.z, fmaf(D, gray, E1));
        oB.z = cut ? 0.0f : fmaf(A, c.z, fmaf(D, gray, E2));

        col = w0 + 3; cut = row_in && (col >= l_) && (col < l_ + CW_);
        gray = (r.w + g.w + c.w) * (1.0f / 3.0f);
        oR.w = cut ? 0.0f : fmaf(A, r.w, fmaf(D, gray, E0));
        oG.w = cut ? 0.0f : fmaf(A, g.w, fmaf(D, gray, E1));
        oB.w = cut ? 0.0f : fmaf(A, c.w, fmaf(D, gray, E2));
    }

    outR[wg] = oR;
    outG[wg] = oG;
    outB[wg] = oB;
}

extern "C" void kernel_launch(void* const* d_in, const int* in_sizes, int n_in,
                              void* d_out, int out_size) {
    const float* images       = (const float*)d_in[0];
    const float* apply_u      = (const float*)d_in[1];
    const float* flip_u       = (const float*)d_in[2];
    const float* brightness_u = (const float*)d_in[3];
    const float* contrast_u   = (const float*)d_in[4];
    const float* saturation_u = (const float*)d_in[5];
    const int*   top_idx      = (const int*)d_in[6];
    const int*   left_idx     = (const int*)d_in[7];
    float* out = (float*)d_out;

    mean_kernel<<<B_ * C_, 256>>>(images);

    dim3 grid(H_ / 4, B_);
    aug_kernel<<<grid, 256>>>(images, apply_u, flip_u, brightness_u,
                              contrast_u, saturation_u, top_idx, left_idx, out);
}